// round 9
// baseline (speedup 1.0000x reference)
#include <cuda_runtime.h>
#include <cuda_bf16.h>
#include <cstdint>

// Problem constants
#define LL 4096
#define DD 1024
#define HH 16
#define PP 4
#define DH 64
#define MM 8192   // B*L

// ---------------------------------------------------------------------------
// Scratch (device globals; no runtime allocation)
// ---------------------------------------------------------------------------
__device__ float         g_v[MM * DD];      // value projection (fp32)
__device__ float         g_off[MM * 128];   // offset projection (exact fp32)
__device__ float         g_attw[MM * 64];   // attention logits (exact fp32)
__device__ __nv_bfloat16 g_ah[MM * DD];     // A operand hi (bf16 split), [M][K]
__device__ __nv_bfloat16 g_al[MM * DD];     // A operand lo
__device__ __nv_bfloat16 g_bh[DD * DD];     // B operand hi, [N][K] (K-major)
__device__ __nv_bfloat16 g_bl[DD * DD];     // B operand lo

// ---------------------------------------------------------------------------
// helpers
// ---------------------------------------------------------------------------
__device__ __forceinline__ uint32_t smem_u32(const void* p) {
    uint32_t a;
    asm("{ .reg .u64 t; cvta.to.shared.u64 t, %1; cvt.u32.u64 %0, t; }" : "=r"(a) : "l"(p));
    return a;
}
__device__ __forceinline__ void cp_async16(uint32_t saddr, const void* gaddr) {
    asm volatile("cp.async.cg.shared.global [%0], [%1], 16;" :: "r"(saddr), "l"(gaddr) : "memory");
}
#define CP_COMMIT()  asm volatile("cp.async.commit_group;" ::: "memory")
#define CP_WAIT(n)   asm volatile("cp.async.wait_group %0;" :: "n"(n) : "memory")

__device__ __forceinline__ void mma_bf16(float c[4], const uint32_t a[4], const uint32_t b[2]) {
    asm volatile(
        "mma.sync.aligned.m16n8k16.row.col.f32.bf16.bf16.f32 "
        "{%0,%1,%2,%3}, {%4,%5,%6,%7}, {%8,%9}, {%0,%1,%2,%3};"
        : "+f"(c[0]), "+f"(c[1]), "+f"(c[2]), "+f"(c[3])
        : "r"(a[0]), "r"(a[1]), "r"(a[2]), "r"(a[3]),
          "r"(b[0]), "r"(b[1]));
}

__device__ __forceinline__ void bsplit(float x, __nv_bfloat16& h, __nv_bfloat16& l) {
    h = __float2bfloat16(x);
    l = __float2bfloat16(x - __bfloat162float(h));
}

// ---------------------------------------------------------------------------
// Elementwise split: fp32 [R x 1024] -> bf16 hi/lo, same layout
// ---------------------------------------------------------------------------
__global__ __launch_bounds__(256) void split_a_kernel(
    const float4* __restrict__ X, __nv_bfloat162* __restrict__ H, __nv_bfloat162* __restrict__ L)
{
    const int g = blockIdx.x * 256 + threadIdx.x;
    float4 v = X[g];
    __nv_bfloat16 h0, l0, h1, l1, h2, l2, h3, l3;
    bsplit(v.x, h0, l0); bsplit(v.y, h1, l1);
    bsplit(v.z, h2, l2); bsplit(v.w, h3, l3);
    H[2 * g + 0] = __nv_bfloat162(h0, h1);
    H[2 * g + 1] = __nv_bfloat162(h2, h3);
    L[2 * g + 0] = __nv_bfloat162(l0, l1);
    L[2 * g + 1] = __nv_bfloat162(l2, l3);
}

// ---------------------------------------------------------------------------
// Transpose + split: W[K=1024][N=1024] fp32 -> BH/BL[N][K] bf16
// ---------------------------------------------------------------------------
__global__ __launch_bounds__(256) void split_bT_kernel(
    const float* __restrict__ W, __nv_bfloat16* __restrict__ BH, __nv_bfloat16* __restrict__ BL)
{
    __shared__ float t[32][33];
    const int tx = threadIdx.x, ty = threadIdx.y;       // (32, 8)
    const int n = blockIdx.x * 32 + tx;
    const int k = blockIdx.y * 32 + ty;
    #pragma unroll
    for (int i = 0; i < 4; i++)
        t[ty + 8 * i][tx] = W[(size_t)(k + 8 * i) * DD + n];
    __syncthreads();
    const int ko = blockIdx.y * 32 + tx;
    const int no = blockIdx.x * 32 + ty;
    #pragma unroll
    for (int i = 0; i < 4; i++) {
        float v = t[tx][ty + 8 * i];
        __nv_bfloat16 h, l;
        bsplit(v, h, l);
        BH[(size_t)(no + 8 * i) * DD + ko] = h;
        BL[(size_t)(no + 8 * i) * DD + ko] = l;
    }
}

// ---------------------------------------------------------------------------
// bf16x3 mma.sync GEMM (R6-proven scalar fragment loads).
// Tile 128x128, BK=32, 2-stage cp.async double buffer, 8 warps, warp 64x32.
// ---------------------------------------------------------------------------
#define RSTR     20                 // row stride in u32 (16 pairs + 4 pad)
#define REG_ELE  (128 * RSTR)       // 2560 u32 per region
#define STG_ELE  (4 * REG_ELE)      // per stage
#define SMEM_G   (2 * STG_ELE * 4)  // 81920 bytes

__global__ __launch_bounds__(256, 2) void gemm_bf16x3_kernel(
    const __nv_bfloat16* __restrict__ Ah, const __nv_bfloat16* __restrict__ Al,
    const __nv_bfloat16* __restrict__ Bh, const __nv_bfloat16* __restrict__ Bl,
    const float* __restrict__ bias, float* __restrict__ C)
{
    extern __shared__ uint32_t S[];
    const uint32_t sb = smem_u32(S);

    const int tid = threadIdx.x, lane = tid & 31, warp = tid >> 5;
    const int wm = (warp >> 2) * 64;
    const int wn = (warp & 3) * 32;
    const int g = lane >> 2, t = lane & 3;
    const int bRow = blockIdx.y * 128, bCol = blockIdx.x * 128;

    const __nv_bfloat16* gptr[4] = {
        Ah + (size_t)bRow * DD, Al + (size_t)bRow * DD,
        Bh + (size_t)bCol * DD, Bl + (size_t)bCol * DD };

    float acc[4][4][4];
    #pragma unroll
    for (int i = 0; i < 4; i++)
        #pragma unroll
        for (int j = 0; j < 4; j++)
            #pragma unroll
            for (int r = 0; r < 4; r++)
                acc[i][j][r] = 0.f;

    auto issue = [&](int c, int buf) {
        const uint32_t sbase = sb + buf * (STG_ELE * 4);
        #pragma unroll
        for (int i = 0; i < 8; i++) {
            const int v = tid + 256 * i;
            const int reg = v >> 9;
            const int u = v & 511;
            const int row = u >> 2;
            const int p4 = u & 3;
            cp_async16(sbase + reg * (REG_ELE * 4) + row * (RSTR * 4) + p4 * 16,
                       gptr[reg] + (size_t)row * DD + c * 32 + p4 * 8);
        }
        CP_COMMIT();
    };

    issue(0, 0);

    for (int c = 0; c < 32; c++) {
        if (c + 1 < 32) { issue(c + 1, (c + 1) & 1); CP_WAIT(1); }
        else            { CP_WAIT(0); }
        __syncthreads();

        const uint32_t* st = S + (c & 1) * STG_ELE;
        const uint32_t* sAh = st;
        const uint32_t* sAl = st + REG_ELE;
        const uint32_t* sBh = st + 2 * REG_ELE;
        const uint32_t* sBl = st + 3 * REG_ELE;

        #pragma unroll
        for (int ks = 0; ks < 2; ks++) {
            const int kp = ks * 8;
            uint32_t afh[4][4], afl[4][4], bfh[4][2], bfl[4][2];
            #pragma unroll
            for (int i = 0; i < 4; i++) {
                const int m0 = wm + i * 16;
                afh[i][0] = sAh[(m0 + g)     * RSTR + kp + t];
                afh[i][1] = sAh[(m0 + g + 8) * RSTR + kp + t];
                afh[i][2] = sAh[(m0 + g)     * RSTR + kp + t + 4];
                afh[i][3] = sAh[(m0 + g + 8) * RSTR + kp + t + 4];
                afl[i][0] = sAl[(m0 + g)     * RSTR + kp + t];
                afl[i][1] = sAl[(m0 + g + 8) * RSTR + kp + t];
                afl[i][2] = sAl[(m0 + g)     * RSTR + kp + t + 4];
                afl[i][3] = sAl[(m0 + g + 8) * RSTR + kp + t + 4];
            }
            #pragma unroll
            for (int j = 0; j < 4; j++) {
                const int n0 = wn + j * 8;
                bfh[j][0] = sBh[(n0 + g) * RSTR + kp + t];
                bfh[j][1] = sBh[(n0 + g) * RSTR + kp + t + 4];
                bfl[j][0] = sBl[(n0 + g) * RSTR + kp + t];
                bfl[j][1] = sBl[(n0 + g) * RSTR + kp + t + 4];
            }
            #pragma unroll
            for (int i = 0; i < 4; i++)
                #pragma unroll
                for (int j = 0; j < 4; j++) {
                    mma_bf16(acc[i][j], afl[i], bfh[j]);
                    mma_bf16(acc[i][j], afh[i], bfl[j]);
                    mma_bf16(acc[i][j], afh[i], bfh[j]);
                }
        }
        __syncthreads();
    }

    // epilogue: c0:(g,2t) c1:(g,2t+1) c2:(g+8,2t) c3:(g+8,2t+1)
    #pragma unroll
    for (int i = 0; i < 4; i++) {
        const int r0 = bRow + wm + i * 16 + g;
        const int r1 = r0 + 8;
        #pragma unroll
        for (int j = 0; j < 4; j++) {
            const int col = bCol + wn + j * 8 + 2 * t;
            const float bz0 = bias[col], bz1 = bias[col + 1];
            float2 o0 = make_float2(acc[i][j][0] + bz0, acc[i][j][1] + bz1);
            float2 o1 = make_float2(acc[i][j][2] + bz0, acc[i][j][3] + bz1);
            *reinterpret_cast<float2*>(C + (size_t)r0 * DD + col) = o0;
            *reinterpret_cast<float2*>(C + (size_t)r1 * DD + col) = o1;
        }
    }
}

// ---------------------------------------------------------------------------
// Exact-fp32 projections (BIT-CRITICAL: per-output k-ascending FMA chain).
// BM=128, BN=64, BK=32, per-thread 8x4. grid (3, 64).
// bx 0,1 -> off col halves; bx 2 -> attw.
// ---------------------------------------------------------------------------
__global__ __launch_bounds__(256) void proj_kernel(
    const float* __restrict__ Q,
    const float* __restrict__ w_off,  const float* __restrict__ b_off,
    const float* __restrict__ w_attw, const float* __restrict__ b_attw,
    float* __restrict__ off_out, float* __restrict__ attw_out)
{
    __shared__ float As[32][128];   // [k][m]
    __shared__ float Bs[32][64];    // [k][n]

    const int tid = threadIdx.x;
    const int bx  = blockIdx.x;
    const int bRow = blockIdx.y * 128;
    const bool isOff = (bx < 2);
    const float* Bm   = isOff ? w_off : w_attw;
    const float* bias = isOff ? b_off : b_attw;
    float* Cp         = isOff ? off_out : attw_out;
    const int NB      = isOff ? 128 : 64;
    const int colBase = isOff ? bx * 64 : 0;

    const int arow = tid >> 1;            // 0..127
    const int acol = (tid & 1) * 16;      // 0 or 16
    const int bkr  = tid >> 3;            // 0..31
    const int bnc  = (tid & 7) * 8;       // 0..56
    const int trow = (tid >> 4) * 8;      // 0..120
    const int tcol = (tid & 15) * 4;      // 0..60

    float acc[8][4];
    #pragma unroll
    for (int i = 0; i < 8; i++)
        #pragma unroll
        for (int j = 0; j < 4; j++)
            acc[i][j] = 0.f;

    const float* Qbase = Q + (size_t)(bRow + arow) * DD;

    for (int k0 = 0; k0 < DD; k0 += 32) {
        #pragma unroll
        for (int q = 0; q < 4; q++) {
            float4 av = *reinterpret_cast<const float4*>(Qbase + k0 + acol + q * 4);
            As[acol + q * 4 + 0][arow] = av.x;
            As[acol + q * 4 + 1][arow] = av.y;
            As[acol + q * 4 + 2][arow] = av.z;
            As[acol + q * 4 + 3][arow] = av.w;
        }
        #pragma unroll
        for (int q = 0; q < 2; q++) {
            float4 bv = *reinterpret_cast<const float4*>(
                Bm + (size_t)(k0 + bkr) * NB + colBase + bnc + q * 4);
            Bs[bkr][bnc + q * 4 + 0] = bv.x;
            Bs[bkr][bnc + q * 4 + 1] = bv.y;
            Bs[bkr][bnc + q * 4 + 2] = bv.z;
            Bs[bkr][bnc + q * 4 + 3] = bv.w;
        }
        __syncthreads();

        #pragma unroll
        for (int kk = 0; kk < 32; kk++) {
            float4 ra0 = *reinterpret_cast<const float4*>(&As[kk][trow]);
            float4 ra1 = *reinterpret_cast<const float4*>(&As[kk][trow + 4]);
            float4 rb  = *reinterpret_cast<const float4*>(&Bs[kk][tcol]);
            float a[8] = {ra0.x, ra0.y, ra0.z, ra0.w, ra1.x, ra1.y, ra1.z, ra1.w};
            float b[4] = {rb.x, rb.y, rb.z, rb.w};
            #pragma unroll
            for (int i = 0; i < 8; i++)
                #pragma unroll
                for (int j = 0; j < 4; j++)
                    acc[i][j] += a[i] * b[j];
        }
        __syncthreads();
    }

    #pragma unroll
    for (int i = 0; i < 8; i++) {
        const int row = bRow + trow + i;
        #pragma unroll
        for (int j = 0; j < 4; j++) {
            const int col = tcol + j;
            Cp[(size_t)row * NB + colBase + col] = acc[i][j] + bias[colBase + col];
        }
    }
}

// ---------------------------------------------------------------------------
// Deformable sampling -> bf16 hi/lo split output (A operand for GEMM2)
// ---------------------------------------------------------------------------
__global__ __launch_bounds__(256) void sample_kernel(
    const float* __restrict__ v, const float* __restrict__ poff,
    const float* __restrict__ pattw,
    __nv_bfloat16* __restrict__ oh, __nv_bfloat16* __restrict__ ol)
{
    const int gwarp = (blockIdx.x * 256 + threadIdx.x) >> 5;
    const int lane  = threadIdx.x & 31;
    if (gwarp >= MM * HH) return;

    const int h   = gwarp & (HH - 1);
    const int row = gwarp >> 4;
    const int b   = row >> 12;
    const int l   = row & (LL - 1);

    float w0 = 0.f, w1 = 0.f;
    int xi0 = 0, xi1 = 0;

    if (lane < PP) {
        const int p = lane;
        float logit = pattw[(size_t)row * 64 + h * PP + p];
        float ox    = poff[(size_t)row * 128 + h * (PP * 2) + p * 2 + 0];
        float oy    = poff[(size_t)row * 128 + h * (PP * 2) + p * 2 + 1];

        float mx = logit;
        mx = fmaxf(mx, __shfl_xor_sync(0xf, mx, 1));
        mx = fmaxf(mx, __shfl_xor_sync(0xf, mx, 2));
        float e = expf(logit - mx);
        float s = e;
        s += __shfl_xor_sync(0xf, s, 1);
        s += __shfl_xor_sync(0xf, s, 2);
        float aw = e / s;

        float ry = (float)l / (float)(LL - 1);
        float sx = fminf(fmaxf(ox, 0.f), 1.f);
        float sy = fminf(fmaxf(ry + oy, 0.f), 1.f);
        float ix = ((sx + 1.f) * (float)LL - 1.f) * 0.5f;
        float iy = ((sy + 1.f) * 1.f - 1.f) * 0.5f;

        float x0f = floorf(ix);
        float fx  = ix - x0f;
        int   x0  = (int)x0f;
        int   x1  = x0 + 1;
        float m0  = (x0 >= 0 && x0 < LL) ? 1.f : 0.f;
        float m1  = (x1 >= 0 && x1 < LL) ? 1.f : 0.f;

        float y0f = floorf(iy);
        float fy  = iy - y0f;
        float hy  = (y0f == 0.f ? 1.f - fy : 0.f) + (y0f == -1.f ? fy : 0.f);

        w0 = aw * (1.f - fx) * m0 * hy;
        w1 = aw * fx * m1 * hy;
        xi0 = min(max(x0, 0), LL - 1);
        xi1 = min(max(x1, 0), LL - 1);
    }

    const float* vb = v + (size_t)b * LL * DD + h * DH + lane;
    float acc0 = 0.f, acc1 = 0.f;

    #pragma unroll
    for (int p = 0; p < PP; p++) {
        float W0 = __shfl_sync(0xffffffff, w0, p);
        float W1 = __shfl_sync(0xffffffff, w1, p);
        int   I0 = __shfl_sync(0xffffffff, xi0, p);
        int   I1 = __shfl_sync(0xffffffff, xi1, p);
        const float* r0 = vb + (size_t)I0 * DD;
        const float* r1 = vb + (size_t)I1 * DD;
        acc0 += W0 * r0[0]  + W1 * r1[0];
        acc1 += W0 * r0[32] + W1 * r1[32];
    }

    __nv_bfloat16 h0, l0, h1, l1;
    bsplit(acc0, h0, l0);
    bsplit(acc1, h1, l1);
    const size_t o = (size_t)row * DD + h * DH + lane;
    oh[o]      = h0;  ol[o]      = l0;
    oh[o + 32] = h1;  ol[o + 32] = l1;
}

// ---------------------------------------------------------------------------
// Launch
// ---------------------------------------------------------------------------
extern "C" void kernel_launch(void* const* d_in, const int* in_sizes, int n_in,
                              void* d_out, int out_size)
{
    const float* query   = (const float*)d_in[0];
    const float* value   = (const float*)d_in[2];
    const float* w_value = (const float*)d_in[5];
    const float* b_value = (const float*)d_in[6];
    const float* w_off   = (const float*)d_in[7];
    const float* b_off   = (const float*)d_in[8];
    const float* w_attw  = (const float*)d_in[9];
    const float* b_attw  = (const float*)d_in[10];
    const float* w_out   = (const float*)d_in[11];
    const float* b_out   = (const float*)d_in[12];
    float* out = (float*)d_out;

    float *v_p, *off_p, *attw_p;
    __nv_bfloat16 *ah_p, *al_p, *bh_p, *bl_p;
    cudaGetSymbolAddress((void**)&v_p,    g_v);
    cudaGetSymbolAddress((void**)&off_p,  g_off);
    cudaGetSymbolAddress((void**)&attw_p, g_attw);
    cudaGetSymbolAddress((void**)&ah_p,   g_ah);
    cudaGetSymbolAddress((void**)&al_p,   g_al);
    cudaGetSymbolAddress((void**)&bh_p,   g_bh);
    cudaGetSymbolAddress((void**)&bl_p,   g_bl);

    cudaFuncSetAttribute(gemm_bf16x3_kernel,
                         cudaFuncAttributeMaxDynamicSharedMemorySize, SMEM_G);

    const dim3 gridGemm(DD / 128, MM / 128);  // (8, 64)
    const dim3 gridT(DD / 32, DD / 32);
    const dim3 blkT(32, 8);

    // 1) operand prep for GEMM1
    split_bT_kernel<<<gridT, blkT>>>(w_value, bh_p, bl_p);
    split_a_kernel<<<MM * DD / 4 / 256, 256>>>(
        (const float4*)value, (__nv_bfloat162*)ah_p, (__nv_bfloat162*)al_p);
    // 2) v = value @ w_value + b  (bf16x3 mma.sync)
    gemm_bf16x3_kernel<<<gridGemm, 256, SMEM_G>>>(ah_p, al_p, bh_p, bl_p, b_value, v_p);
    // 3) exact-fp32 projections
    proj_kernel<<<dim3(3, MM / 128), 256>>>(query, w_off, b_off, w_attw, b_attw, off_p, attw_p);
    // 4) sampling -> bf16 split A for GEMM2
    sample_kernel<<<(MM * HH) / 8, 256>>>(v_p, off_p, attw_p, ah_p, al_p);
    // 5) operand prep for GEMM2
    split_bT_kernel<<<gridT, blkT>>>(w_out, bh_p, bl_p);
    // 6) out = tmp @ w_out + b  (bf16x3 mma.sync)
    gemm_bf16x3_kernel<<<gridGemm, 256, SMEM_G>>>(ah_p, al_p, bh_p, bl_p, b_out, out);
}